// round 1
// baseline (speedup 1.0000x reference)
#include <cuda_runtime.h>
#include <cuda_bf16.h>
#include <cstddef>

// CTRNN: S=2048, B=128, IN=128, H=256, ALPHA=0.1
// outputs[t] = h_t (post-update), h_final = h_{S-1}
//
// Inputs (metadata order): x (S,B,IN), h0 (B,H), W_in (H,IN), b_in (H), W_h (H,H), b_h (H)
// Output: outputs (S,B,H) [+ h_final (B,H) if out_size has room]

#define S_LEN 2048
#define B_DIM 128
#define IN_DIM 128
#define H_DIM 256

// W_h row split per thread: KR columns in registers, KS columns in shared
#define KR4 44              // 176 columns in regs (44 float4)
#define KS4 20              // 80 columns in smem (20 float4)

// Scratch for precomputed input projection (S,B,H) fp32 = 256 MB
__device__ float g_xin[(size_t)S_LEN * B_DIM * H_DIM];

// ---------------------------------------------------------------------------
// Kernel A: xin[s,b,h] = sum_i x[s,b,i] * W_in[h,i] + b_in[h]
// Block = 256 threads (thread j = output column h=j), 64 rows per block.
// W_in row j held in registers (32 float4), x tile in smem (broadcast reads).
// ---------------------------------------------------------------------------
__global__ void __launch_bounds__(256) xin_kernel(
    const float* __restrict__ x,
    const float* __restrict__ Win,
    const float* __restrict__ bin)
{
    __shared__ __align__(16) float4 xs4[64 * 32];   // 64 rows x 128 floats = 32 KB

    const int j = threadIdx.x;
    const size_t rb = (size_t)blockIdx.x * 64;

    // load W_in row j into registers
    const float4* wrow = reinterpret_cast<const float4*>(Win + (size_t)j * IN_DIM);
    float4 wr[32];
#pragma unroll
    for (int i = 0; i < 32; i++) wr[i] = wrow[i];
    const float bias = bin[j];

    // cooperative load of 64 x-rows
    const float4* xg = reinterpret_cast<const float4*>(x + rb * IN_DIM);
#pragma unroll
    for (int i = 0; i < 8; i++) xs4[j + i * 256] = xg[j + i * 256];
    __syncthreads();

    for (int r = 0; r < 64; r++) {
        float acc[4] = {0.f, 0.f, 0.f, 0.f};
#pragma unroll
        for (int k = 0; k < 32; k++) {
            float4 hv = xs4[r * 32 + k];
            float4 w  = wr[k];
            float a = acc[k & 3];
            a = fmaf(w.x, hv.x, a);
            a = fmaf(w.y, hv.y, a);
            a = fmaf(w.z, hv.z, a);
            a = fmaf(w.w, hv.w, a);
            acc[k & 3] = a;
        }
        float dot = (acc[0] + acc[1]) + (acc[2] + acc[3]);
        g_xin[(rb + r) * H_DIM + j] = dot + bias;
    }
}

// ---------------------------------------------------------------------------
// Kernel B: persistent scan. One CTA per batch element (128 CTAs, 1 wave).
// Thread j owns output h[j]. W_h row j: 176 cols in regs, 80 cols in smem.
// h lives in smem (float4-broadcast reads). Full fp32.
// ---------------------------------------------------------------------------
__global__ void __launch_bounds__(256) scan_kernel(
    const float* __restrict__ Wh,
    const float* __restrict__ bh,
    const float* __restrict__ h0,
    float* __restrict__ out,
    int write_final)
{
    extern __shared__ __align__(16) float smem[];
    float4* ws4 = reinterpret_cast<float4*>(smem);        // [KS4 * H_DIM] float4 = 80 KB
    float*  hs  = smem + KS4 * H_DIM * 4;                 // 256 floats

    const int b = blockIdx.x;
    const int j = threadIdx.x;

    // Load W_h row j: first KR4 float4 -> registers, last KS4 -> shared
    const float4* wrow = reinterpret_cast<const float4*>(Wh + (size_t)j * H_DIM);
    float4 wr4[KR4];
#pragma unroll
    for (int i = 0; i < KR4; i++) wr4[i] = wrow[i];
#pragma unroll
    for (int i = 0; i < KS4; i++) ws4[i * H_DIM + j] = wrow[KR4 + i];

    const float bias = bh[j];
    float hj = h0[(size_t)b * H_DIM + j];
    hs[j] = hj;

    const float* xptr = g_xin + (size_t)b * H_DIM + j;
    float xin_cur = xptr[0];
    float* outp = out + (size_t)b * H_DIM + j;
    __syncthreads();

    for (int t = 0; t < S_LEN; t++) {
        // prefetch next timestep's xin (hidden behind the dot product)
        float xin_next = 0.f;
        if (t + 1 < S_LEN) xin_next = xptr[(size_t)(t + 1) * B_DIM * H_DIM];

        const float4* h4 = reinterpret_cast<const float4*>(hs);
        float acc[4] = {0.f, 0.f, 0.f, 0.f};

        // register-resident part of W row
#pragma unroll
        for (int k = 0; k < KR4; k++) {
            float4 hv = h4[k];
            float4 w  = wr4[k];
            float a = acc[k & 3];
            a = fmaf(w.x, hv.x, a);
            a = fmaf(w.y, hv.y, a);
            a = fmaf(w.z, hv.z, a);
            a = fmaf(w.w, hv.w, a);
            acc[k & 3] = a;
        }
        // shared-memory part of W row (conflict-free: lane-consecutive float4)
#pragma unroll
        for (int k = 0; k < KS4; k++) {
            float4 hv = h4[KR4 + k];
            float4 w  = ws4[k * H_DIM + j];
            float a = acc[k & 3];
            a = fmaf(w.x, hv.x, a);
            a = fmaf(w.y, hv.y, a);
            a = fmaf(w.z, hv.z, a);
            a = fmaf(w.w, hv.w, a);
            acc[k & 3] = a;
        }
        float dot = (acc[0] + acc[1]) + (acc[2] + acc[3]);

        __syncthreads();   // all reads of hs done before anyone writes

        float pre  = xin_cur + dot + bias;
        float hnew = fmaxf(pre, 0.f);
        hj = hj * 0.9f + 0.1f * hnew;

        hs[j] = hj;
        outp[(size_t)t * B_DIM * H_DIM] = hj;
        xin_cur = xin_next;

        __syncthreads();   // new hs visible before next iteration's reads
    }

    if (write_final) {
        out[(size_t)S_LEN * B_DIM * H_DIM + (size_t)b * H_DIM + j] = hj;
    }
}

// ---------------------------------------------------------------------------
extern "C" void kernel_launch(void* const* d_in, const int* in_sizes, int n_in,
                              void* d_out, int out_size)
{
    const float* x   = (const float*)d_in[0];
    const float* h0  = (const float*)d_in[1];
    const float* Win = (const float*)d_in[2];
    const float* bin = (const float*)d_in[3];
    const float* Wh  = (const float*)d_in[4];
    const float* bhp = (const float*)d_in[5];
    float* out = (float*)d_out;

    const long long outputs_elems = (long long)S_LEN * B_DIM * H_DIM;
    const int write_final = ((long long)out_size >= outputs_elems + (long long)B_DIM * H_DIM) ? 1 : 0;

    // Kernel A: input projection GEMM -> g_xin
    xin_kernel<<<(S_LEN * B_DIM) / 64, 256>>>(x, Win, bin);

    // Kernel B: sequential scan (persistent, one CTA per batch element)
    const int shm = KS4 * H_DIM * (int)sizeof(float4) + H_DIM * (int)sizeof(float); // 82944 B
    cudaFuncSetAttribute(scan_kernel, cudaFuncAttributeMaxDynamicSharedMemorySize, shm);
    scan_kernel<<<B_DIM, 256, shm>>>(Wh, bhp, h0, out, write_final);
}

// round 2
// speedup vs baseline: 1.2100x; 1.2100x over previous
#include <cuda_runtime.h>
#include <cuda_bf16.h>
#include <cstddef>

// CTRNN: S=2048, B=128, IN=128, H=256, ALPHA=0.1
// Inputs: x (S,B,IN), h0 (B,H), W_in (H,IN), b_in (H), W_h (H,H), b_h (H)
// Output: outputs (S,B,H) [+ h_final (B,H) if room]

#define S_LEN 2048
#define B_DIM 128
#define IN_DIM 128
#define H_DIM 256

typedef unsigned long long u64;

union F2U { u64 u; float2 f; };

// Packed dual-FMA (sm_103a FFMA2). Full fp32 precision per lane.
__device__ __forceinline__ u64 ffma2(u64 a, u64 b, u64 c) {
    u64 d;
    asm("fma.rn.f32x2 %0, %1, %2, %3;" : "=l"(d) : "l"(a), "l"(b), "l"(c));
    return d;
}
__device__ __forceinline__ float f2sum(u64 v) { F2U t; t.u = v; return t.f.x + t.f.y; }

// Scratch for precomputed input projection (S,B,H) fp32 = 256 MB
__device__ float g_xin[(size_t)S_LEN * B_DIM * H_DIM];

// ---------------------------------------------------------------------------
// Kernel A: xin[s,b,h] = sum_i x[s,b,i] * W_in[h,i] + b_in[h]
// 512 threads. Lanes l and l^16 pair on output j = w*16 + (l&15); each handles
// 64 of the 128 K-cols (16 ulonglong2 of W in registers). shfl_xor reduce.
// x tile (64 rows) in smem with mid-row pad to avoid the 2-address bank clash.
// ---------------------------------------------------------------------------
__global__ void __launch_bounds__(512) xin_kernel(
    const float* __restrict__ x,
    const float* __restrict__ Win,
    const float* __restrict__ bin)
{
    // row stride 33 u2: [16 u2 lo][1 u2 pad][16 u2 hi]
    __shared__ __align__(16) ulonglong2 xs[64 * 33];

    const int tid = threadIdx.x;
    const int l = tid & 31, w = tid >> 5;
    const int half = l >> 4;
    const int j = w * 16 + (l & 15);
    const size_t rb = (size_t)blockIdx.x * 64;

    // W_in row j, this thread's 64-col section -> 16 u2 registers
    const ulonglong2* wrow =
        reinterpret_cast<const ulonglong2*>(Win + (size_t)j * IN_DIM + half * 64);
    ulonglong2 wr[16];
#pragma unroll
    for (int i = 0; i < 16; i++) wr[i] = wrow[i];
    const float bias = bin[j];

    // cooperative load: 64 rows x 32 u2, padded layout
    const ulonglong2* xg = reinterpret_cast<const ulonglong2*>(x + rb * IN_DIM);
#pragma unroll
    for (int i = 0; i < 4; i++) {
        int idx = tid + i * 512;
        int r = idx >> 5, c = idx & 31;
        xs[r * 33 + c + (c >= 16 ? 1 : 0)] = xg[idx];
    }
    __syncthreads();

    float* gout = g_xin + rb * H_DIM + j;
    for (int r = 0; r < 64; r++) {
        const ulonglong2* hrow = &xs[r * 33 + half * 17];
        u64 a0 = 0, a1 = 0, a2 = 0, a3 = 0;
#pragma unroll
        for (int k = 0; k < 16; k++) {
            ulonglong2 hv = hrow[k];
            ulonglong2 wv = wr[k];
            if (k & 1) { a2 = ffma2(hv.x, wv.x, a2); a3 = ffma2(hv.y, wv.y, a3); }
            else       { a0 = ffma2(hv.x, wv.x, a0); a1 = ffma2(hv.y, wv.y, a1); }
        }
        float dotp = (f2sum(a0) + f2sum(a1)) + (f2sum(a2) + f2sum(a3));
        float full = dotp + __shfl_xor_sync(0xffffffffu, dotp, 16);
        if (half == 0) gout[(size_t)r * H_DIM] = full + bias;
    }
}

// ---------------------------------------------------------------------------
// Kernel B: persistent scan. One CTA (512 thr) per batch element.
// Lanes l / l^16 pair on output j = w*16+(l&15); each handles 128 K-cols:
// 80 cols (20 u2) of W in registers, 48 cols (12 u2) in smem.
// h double-buffered in smem; ONE __syncthreads per step; shfl_xor(16) reduce.
// ---------------------------------------------------------------------------
#define KRU 20   // ulonglong2 of W in registers per thread (80 cols)
#define KSU 12   // ulonglong2 of W in shared per thread   (48 cols)

__global__ void __launch_bounds__(512) scan_kernel(
    const float* __restrict__ Wh,
    const float* __restrict__ bh,
    const float* __restrict__ h0,
    float* __restrict__ out,
    int write_final)
{
    extern __shared__ __align__(16) char smraw[];
    ulonglong2* ws = reinterpret_cast<ulonglong2*>(smraw);          // [KSU*512] = 96 KB
    float* hsm = reinterpret_cast<float*>(smraw + KSU * 512 * 16);  // 2 buffers x 264 floats
    // buffer layout: [0..127]=h[0:128], 4-float pad, [132..259]=h[128:256]

    const int b = blockIdx.x;
    const int tid = threadIdx.x;
    const int l = tid & 31, w = tid >> 5;
    const int half = l >> 4;
    const int j = w * 16 + (l & 15);

    // W_h row j, this thread's 128-col section: 20 u2 regs + 12 u2 smem
    const ulonglong2* wrow =
        reinterpret_cast<const ulonglong2*>(Wh + (size_t)j * H_DIM + half * 128);
    ulonglong2 wr[KRU];
#pragma unroll
    for (int i = 0; i < KRU; i++) wr[i] = wrow[i];
#pragma unroll
    for (int i = 0; i < KSU; i++) ws[i * 512 + tid] = wrow[KRU + i];

    const float bias = bh[j];
    float hj = h0[(size_t)b * H_DIM + j];
    const int widx = (j < 128) ? j : (j + 4);
    if (half == 0) hsm[widx] = hj;     // buffer 0

    const float* xptr = g_xin + (size_t)b * H_DIM + j;
    float xin_cur = xptr[0];
    float* outp = out + (size_t)b * H_DIM + j;
    int buf = 0;
    __syncthreads();

    for (int t = 0; t < S_LEN; t++) {
        // prefetch next timestep's xin behind the dot product
        float xin_next = 0.f;
        if (t + 1 < S_LEN) xin_next = xptr[(size_t)(t + 1) * B_DIM * H_DIM];

        const ulonglong2* hA = reinterpret_cast<const ulonglong2*>(
            hsm + buf * 264 + (half ? 132 : 0));

        u64 a0 = 0, a1 = 0, a2 = 0, a3 = 0;
#pragma unroll
        for (int k = 0; k < KRU; k++) {
            ulonglong2 hv = hA[k];
            ulonglong2 wv = wr[k];
            if (k & 1) { a2 = ffma2(hv.x, wv.x, a2); a3 = ffma2(hv.y, wv.y, a3); }
            else       { a0 = ffma2(hv.x, wv.x, a0); a1 = ffma2(hv.y, wv.y, a1); }
        }
#pragma unroll
        for (int k = 0; k < KSU; k++) {
            ulonglong2 hv = hA[KRU + k];
            ulonglong2 wv = ws[k * 512 + tid];
            if (k & 1) { a2 = ffma2(hv.x, wv.x, a2); a3 = ffma2(hv.y, wv.y, a3); }
            else       { a0 = ffma2(hv.x, wv.x, a0); a1 = ffma2(hv.y, wv.y, a1); }
        }
        float dotp = (f2sum(a0) + f2sum(a1)) + (f2sum(a2) + f2sum(a3));
        float full = dotp + __shfl_xor_sync(0xffffffffu, dotp, 16);

        float pre  = xin_cur + full + bias;
        float hnew = fmaxf(pre, 0.f);
        hj = hj * 0.9f + 0.1f * hnew;

        if (half == 0) {
            hsm[(buf ^ 1) * 264 + widx] = hj;
            outp[(size_t)t * B_DIM * H_DIM] = hj;
        }
        xin_cur = xin_next;
        buf ^= 1;
        __syncthreads();   // single barrier: step t writes (buf^1) before step t+1 reads it
    }

    if (write_final && half == 0) {
        out[(size_t)S_LEN * B_DIM * H_DIM + (size_t)b * H_DIM + j] = hj;
    }
}

// ---------------------------------------------------------------------------
extern "C" void kernel_launch(void* const* d_in, const int* in_sizes, int n_in,
                              void* d_out, int out_size)
{
    const float* x   = (const float*)d_in[0];
    const float* h0  = (const float*)d_in[1];
    const float* Win = (const float*)d_in[2];
    const float* bin = (const float*)d_in[3];
    const float* Wh  = (const float*)d_in[4];
    const float* bhp = (const float*)d_in[5];
    float* out = (float*)d_out;

    const long long outputs_elems = (long long)S_LEN * B_DIM * H_DIM;
    const int write_final =
        ((long long)out_size >= outputs_elems + (long long)B_DIM * H_DIM) ? 1 : 0;

    // Kernel A: input projection GEMM -> g_xin
    xin_kernel<<<(S_LEN * B_DIM) / 64, 512>>>(x, Win, bin);

    // Kernel B: sequential scan (one CTA per batch element)
    const int shm = KSU * 512 * (int)sizeof(ulonglong2) + 2 * 264 * (int)sizeof(float);
    cudaFuncSetAttribute(scan_kernel, cudaFuncAttributeMaxDynamicSharedMemorySize, shm);
    scan_kernel<<<B_DIM, 512, shm>>>(Wh, bhp, h0, out, write_final);
}